// round 1
// baseline (speedup 1.0000x reference)
#include <cuda_runtime.h>

// GenerateNodes: out[m,o,k] = sum_c mix[m,c] * W[k,o,c] + b[k,o]
//   m in [0,16384), mix = concat(x[m,0:3200], seeds[m,0:15]), j = k*3+o in [0,60)
// FMA2 (packed f32x2) register-blocked kernel. Deterministic, single launch.

#define NROWS   16384
#define KX      3200
#define KS      15
#define KTOT    3215
#define JDIM    60      // 20 nodes * 3 channels
#define ROWS_PC 32      // rows per CTA
#define CHUNK   64      // c-columns per CTA chunk
#define WCH     16      // c-columns per warp per chunk
#define NCHUNK  50      // 3200 / 64
#define XS_STR  33      // padded row stride for transposed x tile

typedef unsigned long long ull;

__device__ __forceinline__ ull fma2(ull a, ull b, ull c) {
    ull d;
    asm("fma.rn.f32x2 %0, %1, %2, %3;" : "=l"(d) : "l"(a), "l"(b), "l"(c));
    return d;
}
__device__ __forceinline__ ull pack2(float lo, float hi) {
    ull d;
    asm("mov.b64 %0, {%1, %2};" : "=l"(d) : "f"(lo), "f"(hi));
    return d;
}
__device__ __forceinline__ float2 unpack2(ull v) {
    float2 r;
    asm("mov.b64 {%0, %1}, %2;" : "=f"(r.x), "=f"(r.y) : "l"(v));
    return r;
}

__global__ __launch_bounds__(128)
void gen_nodes_kernel(const float* __restrict__ x,
                      const float* __restrict__ seeds,
                      const float* __restrict__ W,
                      const float* __restrict__ b,
                      float* __restrict__ out)
{
    // smem: xs (transposed x tile) | ws (transposed W tile). red aliases xs.
    __shared__ float smem[CHUNK * XS_STR + CHUNK * JDIM];
    float* xs = smem;                       // [CHUNK][XS_STR] -> xs[c][row]
    float* ws = smem + CHUNK * XS_STR;      // [CHUNK][JDIM]   -> ws[c][j]
    float* red = smem;                      // [ROWS_PC][JDIM], 1920 <= 2112 floats

    const int tid  = threadIdx.x;
    const int lane = tid & 31;
    const int warp = tid >> 5;
    const int row0 = blockIdx.x * ROWS_PC;

    ull acc[JDIM / 2];
    #pragma unroll
    for (int i = 0; i < JDIM / 2; i++) acc[i] = 0ull;

    for (int ch = 0; ch <= NCHUNK; ch++) {
        const int cbase = ch * CHUNK;
        const int width = (ch < NCHUNK) ? CHUNK : KS;

        __syncthreads();  // smem reuse guard vs previous chunk's compute

        // ---- load x/seeds tile, transposed to xs[c_local][row] ----
        if (ch < NCHUNK) {
            #pragma unroll
            for (int i = 0; i < 4; i++) {
                int idx = tid + i * 128;            // 0..511 float4s
                int r   = idx >> 4;                 // row 0..31
                int cq  = idx & 15;                 // float4 index within 64 c's
                const float4 v = *reinterpret_cast<const float4*>(
                    x + (size_t)(row0 + r) * KX + cbase + 4 * cq);
                xs[(4 * cq + 0) * XS_STR + r] = v.x;
                xs[(4 * cq + 1) * XS_STR + r] = v.y;
                xs[(4 * cq + 2) * XS_STR + r] = v.z;
                xs[(4 * cq + 3) * XS_STR + r] = v.w;
            }
        } else {
            for (int idx = tid; idx < ROWS_PC * KS; idx += 128) {
                int r = idx / KS, c = idx - r * KS;
                xs[c * XS_STR + r] = seeds[(size_t)(row0 + r) * KS + c];
            }
        }

        // ---- load W tile, transposed to ws[c_local][j] ----
        for (int idx = tid; idx < width * JDIM; idx += 128) {
            int j = idx / width, cl = idx - j * width;
            ws[cl * JDIM + j] = W[(size_t)j * KTOT + cbase + cl];
        }

        __syncthreads();

        // ---- compute: warp handles its c sub-range of this chunk ----
        int k0, k1;
        if (ch < NCHUNK) { k0 = warp * WCH; k1 = k0 + WCH; }
        else             { k0 = warp * 4;   k1 = (k0 + 4 < KS) ? (k0 + 4) : KS; }

        #pragma unroll 4
        for (int cl = k0; cl < k1; cl++) {
            const float m = xs[cl * XS_STR + lane];
            const ull  mm = pack2(m, m);
            const ulonglong2* wrow =
                reinterpret_cast<const ulonglong2*>(&ws[cl * JDIM]);
            #pragma unroll
            for (int q = 0; q < 15; q++) {
                ulonglong2 wv = wrow[q];   // LDS.128 broadcast: w[4q..4q+3]
                acc[2 * q]     = fma2(mm, wv.x, acc[2 * q]);
                acc[2 * q + 1] = fma2(mm, wv.y, acc[2 * q + 1]);
            }
        }
    }

    // ---- deterministic cross-warp reduction into smem ----
    __syncthreads();
    for (int w = 0; w < 4; w++) {
        if (warp == w) {
            #pragma unroll
            for (int q = 0; q < JDIM / 2; q++) {
                float2 v = unpack2(acc[q]);
                float2* p = reinterpret_cast<float2*>(&red[lane * JDIM + 2 * q]);
                if (w == 0) {
                    *p = v;
                } else {
                    float2 old = *p;
                    old.x += v.x; old.y += v.y;
                    *p = old;
                }
            }
        }
        __syncthreads();
    }

    // ---- fused bias + [o,node] permute, fully coalesced store ----
    const size_t obase = (size_t)row0 * JDIM;
    for (int idx = tid; idx < ROWS_PC * JDIM; idx += 128) {
        int r    = idx / JDIM;
        int pos  = idx - r * JDIM;        // = o*20 + node
        int o    = pos / 20;
        int node = pos - o * 20;
        int j    = node * 3 + o;          // W/bias row index
        out[obase + idx] = red[r * JDIM + j] + b[j];
    }
}

extern "C" void kernel_launch(void* const* d_in, const int* in_sizes, int n_in,
                              void* d_out, int out_size)
{
    const float* x     = (const float*)d_in[0];
    const float* seeds = (const float*)d_in[1];
    const float* W     = (const float*)d_in[2];
    const float* b     = (const float*)d_in[3];
    float*       out   = (float*)d_out;

    gen_nodes_kernel<<<NROWS / ROWS_PC, 128>>>(x, seeds, W, b, out);
}